// round 2
// baseline (speedup 1.0000x reference)
#include <cuda_runtime.h>
#include <cuda_bf16.h>
#include <math.h>
#include <stdint.h>

#define BB 4
#define LL 2048
#define DM 512
#define NH 8
#define DKV 64
#define MTOT (BB*LL)   // 8192

// ---------------- scratch (no allocations allowed) ----------------
__device__ float g_qh[(size_t)MTOT*DM];
__device__ float g_kh[(size_t)MTOT*DM];
__device__ float g_vh[(size_t)MTOT*DM];
__device__ float g_ao[(size_t)MTOT*DM];
__device__ float g_fc[(size_t)MTOT*DM];

// ---------------- GEMM: C[M,N] = A[M,K] @ W[N,K]^T + bias (+res) ----------------
__global__ void __launch_bounds__(256)
gemm_kernel(const float* __restrict__ A, const float* __restrict__ W,
            const float* __restrict__ bias, const float* __restrict__ res,
            float* __restrict__ C, int M, int N, int K)
{
    __shared__ __align__(16) float As[16*68];
    __shared__ __align__(16) float Ws[16*68];
    const int tid = threadIdx.x;
    const int tx = tid & 15, ty = tid >> 4;
    const int n0 = blockIdx.x * 64, m0 = blockIdx.y * 64;

    float acc[4][4] = {};

    for (int k0 = 0; k0 < K; k0 += 16) {
        #pragma unroll
        for (int r = 0; r < 4; r++) {
            int idx = tid + 256*r;
            int m = idx >> 4, kk = idx & 15;
            As[kk*68 + m] = A[(size_t)(m0+m)*K + k0 + kk];
            Ws[kk*68 + m] = W[(size_t)(n0+m)*K + k0 + kk];
        }
        __syncthreads();
        #pragma unroll
        for (int kk = 0; kk < 16; kk++) {
            float4 a4 = *(const float4*)&As[kk*68 + ty*4];
            float4 b4 = *(const float4*)&Ws[kk*68 + tx*4];
            float av[4] = {a4.x, a4.y, a4.z, a4.w};
            float bv[4] = {b4.x, b4.y, b4.z, b4.w};
            #pragma unroll
            for (int i = 0; i < 4; i++)
                #pragma unroll
                for (int j = 0; j < 4; j++)
                    acc[i][j] = fmaf(av[i], bv[j], acc[i][j]);
        }
        __syncthreads();
    }

    #pragma unroll
    for (int i = 0; i < 4; i++) {
        int m = m0 + ty*4 + i;
        #pragma unroll
        for (int j = 0; j < 4; j++) {
            int n = n0 + tx*4 + j;
            float v = acc[i][j] + bias[n];
            if (res) v += res[(size_t)m*N + n];
            C[(size_t)m*N + n] = v;
        }
    }
}

// ---------------- Fused attention ----------------
#define QT 16
#define KT 64
#define KPAD 68
#define ATTN_SMEM ((QT*LL + KT*KPAD + QT*64 + QT) * 4)

__global__ void __launch_bounds__(256)
attn_kernel(const float* __restrict__ qh, const float* __restrict__ kh,
            const float* __restrict__ vh, const int* __restrict__ mask,
            float* __restrict__ attn_out, float* __restrict__ ao)
{
    extern __shared__ __align__(16) float sm[];
    float* ss  = sm;                    // QT * LL  (scores, then exp)
    float* kt  = ss + QT*LL;            // KT * KPAD (K tile, reused for V)
    float* qt  = kt + KT*KPAD;          // QT * 64
    float* inv = qt + QT*64;            // QT

    const int tid = threadIdx.x;
    const int q0 = blockIdx.x * QT;
    const int h  = blockIdx.y;
    const int b  = blockIdx.z;

    const float* qbase = qh + (size_t)b*LL*DM + h*DKV;
    const float* kbase = kh + (size_t)b*LL*DM + h*DKV;
    const float* vbase = vh + (size_t)b*LL*DM + h*DKV;
    const int* mbase = mask + (size_t)b*LL*LL;

    // load Q tile
    for (int i = tid; i < QT*64; i += 256) {
        int qi = i >> 6, d = i & 63;
        qt[qi*64 + d] = qbase[(size_t)(q0+qi)*DM + d];
    }

    // ---- scores: each thread = 1 row x 4 cols ----
    const int qi_s = tid >> 4;
    const int cb   = tid & 15;
    for (int t = 0; t < LL; t += KT) {
        for (int i = tid; i < KT*64; i += 256) {
            int kk = i >> 6, d = i & 63;
            kt[kk*KPAD + d] = kbase[(size_t)(t+kk)*DM + d];
        }
        __syncthreads();
        float acc[4] = {0.f, 0.f, 0.f, 0.f};
        #pragma unroll
        for (int d = 0; d < 64; d += 4) {
            float4 qv = *(const float4*)&qt[qi_s*64 + d];
            #pragma unroll
            for (int c = 0; c < 4; c++) {
                float4 kv = *(const float4*)&kt[(cb + 16*c)*KPAD + d];
                acc[c] = fmaf(qv.x, kv.x, acc[c]);
                acc[c] = fmaf(qv.y, kv.y, acc[c]);
                acc[c] = fmaf(qv.z, kv.z, acc[c]);
                acc[c] = fmaf(qv.w, kv.w, acc[c]);
            }
        }
        #pragma unroll
        for (int c = 0; c < 4; c++) {
            int k = t + cb + 16*c;
            float s = acc[c] * 0.125f;
            if (mbase[(size_t)(q0+qi_s)*LL + k]) s = -INFINITY;
            ss[qi_s*LL + k] = s;
        }
        __syncthreads();
    }

    // ---- softmax: one warp per 2 rows ----
    {
        const int warp = tid >> 5, lane = tid & 31;
        for (int row = warp; row < QT; row += 8) {
            float m = -INFINITY;
            for (int k = lane; k < LL; k += 32) m = fmaxf(m, ss[row*LL + k]);
            #pragma unroll
            for (int o = 16; o; o >>= 1) m = fmaxf(m, __shfl_xor_sync(0xffffffffu, m, o));
            float s = 0.f;
            for (int k = lane; k < LL; k += 32) {
                float e = __expf(ss[row*LL + k] - m);
                ss[row*LL + k] = e;
                s += e;
            }
            #pragma unroll
            for (int o = 16; o; o >>= 1) s += __shfl_xor_sync(0xffffffffu, s, o);
            if (lane == 0) inv[row] = 1.0f / s;
        }
    }
    __syncthreads();

    // ---- write normalized attention: attn_flat[(h*B+b), q, k] ----
    {
        float* aout = attn_out + (((size_t)h*BB + b)*LL + q0)*LL;
        for (int i = tid; i < QT*LL; i += 256) {
            int qi = i >> 11;  // / 2048
            aout[i] = ss[i] * inv[qi];
        }
    }

    // ---- AV: each thread = 1 row x 4 output dims ----
    const int qi_v = tid >> 4;
    const int d4   = (tid & 15) * 4;
    float o0 = 0.f, o1 = 0.f, o2 = 0.f, o3 = 0.f;
    for (int t = 0; t < LL; t += KT) {
        __syncthreads();
        for (int i = tid; i < KT*64; i += 256) {
            int kk = i >> 6, d = i & 63;
            kt[kk*KPAD + d] = vbase[(size_t)(t+kk)*DM + d];
        }
        __syncthreads();
        #pragma unroll
        for (int kk = 0; kk < KT; kk += 4) {
            float4 p  = *(const float4*)&ss[qi_v*LL + t + kk];
            float4 a0 = *(const float4*)&kt[(kk+0)*KPAD + d4];
            float4 a1 = *(const float4*)&kt[(kk+1)*KPAD + d4];
            float4 a2 = *(const float4*)&kt[(kk+2)*KPAD + d4];
            float4 a3 = *(const float4*)&kt[(kk+3)*KPAD + d4];
            o0 = fmaf(p.x, a0.x, o0); o0 = fmaf(p.y, a1.x, o0); o0 = fmaf(p.z, a2.x, o0); o0 = fmaf(p.w, a3.x, o0);
            o1 = fmaf(p.x, a0.y, o1); o1 = fmaf(p.y, a1.y, o1); o1 = fmaf(p.z, a2.y, o1); o1 = fmaf(p.w, a3.y, o1);
            o2 = fmaf(p.x, a0.z, o2); o2 = fmaf(p.y, a1.z, o2); o2 = fmaf(p.z, a2.z, o2); o2 = fmaf(p.w, a3.z, o2);
            o3 = fmaf(p.x, a0.w, o3); o3 = fmaf(p.y, a1.w, o3); o3 = fmaf(p.z, a2.w, o3); o3 = fmaf(p.w, a3.w, o3);
        }
    }
    {
        float sc = inv[qi_v];
        float4 r = make_float4(o0*sc, o1*sc, o2*sc, o3*sc);
        *(float4*)&ao[((size_t)b*LL + q0 + qi_v)*DM + h*DKV + d4] = r;
    }
}

// ---------------- LayerNorm over rows of 512 ----------------
__global__ void __launch_bounds__(256)
ln_kernel(const float* __restrict__ x, const float* __restrict__ g,
          const float* __restrict__ be, float* __restrict__ out)
{
    const int row = blockIdx.x;
    const int tid = threadIdx.x;
    const float* xr = x + (size_t)row * DM;

    float v0 = xr[tid], v1 = xr[tid + 256];
    float s = v0 + v1;
    float sq = v0*v0 + v1*v1;

    __shared__ float rs[8], rq[8];
    #pragma unroll
    for (int o = 16; o; o >>= 1) {
        s  += __shfl_xor_sync(0xffffffffu, s,  o);
        sq += __shfl_xor_sync(0xffffffffu, sq, o);
    }
    const int warp = tid >> 5, lane = tid & 31;
    if (lane == 0) { rs[warp] = s; rq[warp] = sq; }
    __syncthreads();
    __shared__ float mu_s, rstd_s;
    if (tid == 0) {
        float S = 0.f, Q = 0.f;
        #pragma unroll
        for (int w = 0; w < 8; w++) { S += rs[w]; Q += rq[w]; }
        float mu = S * (1.0f / DM);
        float var = Q * (1.0f / DM) - mu * mu;
        mu_s = mu;
        rstd_s = rsqrtf(var + 1e-5f);
    }
    __syncthreads();
    float mu = mu_s, rstd = rstd_s;
    out[(size_t)row*DM + tid]       = (v0 - mu) * rstd * g[tid]       + be[tid];
    out[(size_t)row*DM + tid + 256] = (v1 - mu) * rstd * g[tid + 256] + be[tid + 256];
}

// ---------------- launch ----------------
extern "C" void kernel_launch(void* const* d_in, const int* in_sizes, int n_in,
                              void* d_out, int out_size)
{
    const float* q    = (const float*)d_in[0];
    const float* k    = (const float*)d_in[1];
    const float* v    = (const float*)d_in[2];
    const int*   mask = (const int*)d_in[3];
    const float* wq_w = (const float*)d_in[4];
    const float* wq_b = (const float*)d_in[5];
    const float* wk_w = (const float*)d_in[6];
    const float* wk_b = (const float*)d_in[7];
    const float* wv_w = (const float*)d_in[8];
    const float* wv_b = (const float*)d_in[9];
    const float* fc_w = (const float*)d_in[10];
    const float* fc_b = (const float*)d_in[11];
    const float* ln_g = (const float*)d_in[12];
    const float* ln_b = (const float*)d_in[13];

    float* out      = (float*)d_out;                       // [B, L, 512]
    float* attn_out = out + (size_t)MTOT * DM;             // [H*B, L, L]

    float *qh, *kh, *vh, *ao, *fc;
    cudaGetSymbolAddress((void**)&qh, g_qh);
    cudaGetSymbolAddress((void**)&kh, g_kh);
    cudaGetSymbolAddress((void**)&vh, g_vh);
    cudaGetSymbolAddress((void**)&ao, g_ao);
    cudaGetSymbolAddress((void**)&fc, g_fc);

    cudaFuncSetAttribute(attn_kernel, cudaFuncAttributeMaxDynamicSharedMemorySize, ATTN_SMEM);

    dim3 ggrid(DM/64, MTOT/64);
    gemm_kernel<<<ggrid, 256>>>(q, wq_w, wq_b, nullptr, qh, MTOT, DM, DM);
    gemm_kernel<<<ggrid, 256>>>(k, wk_w, wk_b, nullptr, kh, MTOT, DM, DM);
    gemm_kernel<<<ggrid, 256>>>(v, wv_w, wv_b, nullptr, vh, MTOT, DM, DM);

    dim3 agrid(LL/QT, NH, BB);
    attn_kernel<<<agrid, 256, ATTN_SMEM>>>(qh, kh, vh, mask, attn_out, ao);

    gemm_kernel<<<ggrid, 256>>>(ao, fc_w, fc_b, q, fc, MTOT, DM, DM);

    ln_kernel<<<MTOT, 256>>>(fc, ln_g, ln_b, out);
}

// round 3
// speedup vs baseline: 1.0007x; 1.0007x over previous
#include <cuda_runtime.h>
#include <cuda_bf16.h>
#include <math.h>
#include <stdint.h>

#define BB 4
#define LL 2048
#define DM 512
#define NH 8
#define DKV 64
#define MTOT (BB*LL)   // 8192

// ---------------- scratch (no allocations allowed) ----------------
__device__ float g_qh[(size_t)MTOT*DM];
__device__ float g_kh[(size_t)MTOT*DM];
__device__ float g_vh[(size_t)MTOT*DM];
__device__ float g_ao[(size_t)MTOT*DM];
__device__ float g_fc[(size_t)MTOT*DM];

// ---------------- GEMM: C[M,N] = A[M,K] @ W[N,K]^T + bias (+res) ----------------
__global__ void __launch_bounds__(256)
gemm_kernel(const float* __restrict__ A, const float* __restrict__ W,
            const float* __restrict__ bias, const float* __restrict__ res,
            float* __restrict__ C, int M, int N, int K)
{
    __shared__ __align__(16) float As[16*68];
    __shared__ __align__(16) float Ws[16*68];
    const int tid = threadIdx.x;
    const int tx = tid & 15, ty = tid >> 4;
    const int n0 = blockIdx.x * 64, m0 = blockIdx.y * 64;

    float acc[4][4] = {};

    for (int k0 = 0; k0 < K; k0 += 16) {
        #pragma unroll
        for (int r = 0; r < 4; r++) {
            int idx = tid + 256*r;
            int m = idx >> 4, kk = idx & 15;
            As[kk*68 + m] = A[(size_t)(m0+m)*K + k0 + kk];
            Ws[kk*68 + m] = W[(size_t)(n0+m)*K + k0 + kk];
        }
        __syncthreads();
        #pragma unroll
        for (int kk = 0; kk < 16; kk++) {
            float4 a4 = *(const float4*)&As[kk*68 + ty*4];
            float4 b4 = *(const float4*)&Ws[kk*68 + tx*4];
            float av[4] = {a4.x, a4.y, a4.z, a4.w};
            float bv[4] = {b4.x, b4.y, b4.z, b4.w};
            #pragma unroll
            for (int i = 0; i < 4; i++)
                #pragma unroll
                for (int j = 0; j < 4; j++)
                    acc[i][j] = fmaf(av[i], bv[j], acc[i][j]);
        }
        __syncthreads();
    }

    #pragma unroll
    for (int i = 0; i < 4; i++) {
        int m = m0 + ty*4 + i;
        #pragma unroll
        for (int j = 0; j < 4; j++) {
            int n = n0 + tx*4 + j;
            float v = acc[i][j] + bias[n];
            if (res) v += res[(size_t)m*N + n];
            C[(size_t)m*N + n] = v;
        }
    }
}

// ---------------- Fused attention ----------------
#define QT 16
#define KT 64
#define KPAD 68
#define ATTN_SMEM ((QT*LL + KT*KPAD + QT*64 + QT) * 4)

__global__ void __launch_bounds__(256)
attn_kernel(const float* __restrict__ qh, const float* __restrict__ kh,
            const float* __restrict__ vh, const int* __restrict__ mask,
            float* __restrict__ attn_out, float* __restrict__ ao)
{
    extern __shared__ __align__(16) float sm[];
    float* ss  = sm;                    // QT * LL  (scores, then exp)
    float* kt  = ss + QT*LL;            // KT * KPAD (K tile, reused for V)
    float* qt  = kt + KT*KPAD;          // QT * 64
    float* inv = qt + QT*64;            // QT

    const int tid = threadIdx.x;
    const int q0 = blockIdx.x * QT;
    const int h  = blockIdx.y;
    const int b  = blockIdx.z;

    const float* qbase = qh + (size_t)b*LL*DM + h*DKV;
    const float* kbase = kh + (size_t)b*LL*DM + h*DKV;
    const float* vbase = vh + (size_t)b*LL*DM + h*DKV;
    const int* mbase = mask + (size_t)b*LL*LL;

    // load Q tile
    for (int i = tid; i < QT*64; i += 256) {
        int qi = i >> 6, d = i & 63;
        qt[qi*64 + d] = qbase[(size_t)(q0+qi)*DM + d];
    }

    // ---- scores: each thread = 1 row x 4 cols ----
    const int qi_s = tid >> 4;
    const int cb   = tid & 15;
    for (int t = 0; t < LL; t += KT) {
        for (int i = tid; i < KT*64; i += 256) {
            int kk = i >> 6, d = i & 63;
            kt[kk*KPAD + d] = kbase[(size_t)(t+kk)*DM + d];
        }
        __syncthreads();
        float acc[4] = {0.f, 0.f, 0.f, 0.f};
        #pragma unroll
        for (int d = 0; d < 64; d += 4) {
            float4 qv = *(const float4*)&qt[qi_s*64 + d];
            #pragma unroll
            for (int c = 0; c < 4; c++) {
                float4 kv = *(const float4*)&kt[(cb + 16*c)*KPAD + d];
                acc[c] = fmaf(qv.x, kv.x, acc[c]);
                acc[c] = fmaf(qv.y, kv.y, acc[c]);
                acc[c] = fmaf(qv.z, kv.z, acc[c]);
                acc[c] = fmaf(qv.w, kv.w, acc[c]);
            }
        }
        #pragma unroll
        for (int c = 0; c < 4; c++) {
            int k = t + cb + 16*c;
            float s = acc[c] * 0.125f;
            if (mbase[(size_t)(q0+qi_s)*LL + k]) s = -INFINITY;
            ss[qi_s*LL + k] = s;
        }
        __syncthreads();
    }

    // ---- softmax: one warp per 2 rows ----
    {
        const int warp = tid >> 5, lane = tid & 31;
        for (int row = warp; row < QT; row += 8) {
            float m = -INFINITY;
            for (int k = lane; k < LL; k += 32) m = fmaxf(m, ss[row*LL + k]);
            #pragma unroll
            for (int o = 16; o; o >>= 1) m = fmaxf(m, __shfl_xor_sync(0xffffffffu, m, o));
            float s = 0.f;
            for (int k = lane; k < LL; k += 32) {
                float e = __expf(ss[row*LL + k] - m);
                ss[row*LL + k] = e;
                s += e;
            }
            #pragma unroll
            for (int o = 16; o; o >>= 1) s += __shfl_xor_sync(0xffffffffu, s, o);
            if (lane == 0) inv[row] = 1.0f / s;
        }
    }
    __syncthreads();

    // ---- write normalized attention: attn_flat[(h*B+b), q, k] ----
    {
        float* aout = attn_out + (((size_t)h*BB + b)*LL + q0)*LL;
        for (int i = tid; i < QT*LL; i += 256) {
            int qi = i >> 11;  // / 2048
            aout[i] = ss[i] * inv[qi];
        }
    }

    // ---- AV: each thread = 1 row x 4 output dims ----
    const int qi_v = tid >> 4;
    const int d4   = (tid & 15) * 4;
    float o0 = 0.f, o1 = 0.f, o2 = 0.f, o3 = 0.f;
    for (int t = 0; t < LL; t += KT) {
        __syncthreads();
        for (int i = tid; i < KT*64; i += 256) {
            int kk = i >> 6, d = i & 63;
            kt[kk*KPAD + d] = vbase[(size_t)(t+kk)*DM + d];
        }
        __syncthreads();
        #pragma unroll
        for (int kk = 0; kk < KT; kk += 4) {
            float4 p  = *(const float4*)&ss[qi_v*LL + t + kk];
            float4 a0 = *(const float4*)&kt[(kk+0)*KPAD + d4];
            float4 a1 = *(const float4*)&kt[(kk+1)*KPAD + d4];
            float4 a2 = *(const float4*)&kt[(kk+2)*KPAD + d4];
            float4 a3 = *(const float4*)&kt[(kk+3)*KPAD + d4];
            o0 = fmaf(p.x, a0.x, o0); o0 = fmaf(p.y, a1.x, o0); o0 = fmaf(p.z, a2.x, o0); o0 = fmaf(p.w, a3.x, o0);
            o1 = fmaf(p.x, a0.y, o1); o1 = fmaf(p.y, a1.y, o1); o1 = fmaf(p.z, a2.y, o1); o1 = fmaf(p.w, a3.y, o1);
            o2 = fmaf(p.x, a0.z, o2); o2 = fmaf(p.y, a1.z, o2); o2 = fmaf(p.z, a2.z, o2); o2 = fmaf(p.w, a3.z, o2);
            o3 = fmaf(p.x, a0.w, o3); o3 = fmaf(p.y, a1.w, o3); o3 = fmaf(p.z, a2.w, o3); o3 = fmaf(p.w, a3.w, o3);
        }
    }
    {
        float sc = inv[qi_v];
        float4 r = make_float4(o0*sc, o1*sc, o2*sc, o3*sc);
        *(float4*)&ao[((size_t)b*LL + q0 + qi_v)*DM + h*DKV + d4] = r;
    }
}

// ---------------- LayerNorm over rows of 512 ----------------
__global__ void __launch_bounds__(256)
ln_kernel(const float* __restrict__ x, const float* __restrict__ g,
          const float* __restrict__ be, float* __restrict__ out)
{
    const int row = blockIdx.x;
    const int tid = threadIdx.x;
    const float* xr = x + (size_t)row * DM;

    float v0 = xr[tid], v1 = xr[tid + 256];
    float s = v0 + v1;
    float sq = v0*v0 + v1*v1;

    __shared__ float rs[8], rq[8];
    #pragma unroll
    for (int o = 16; o; o >>= 1) {
        s  += __shfl_xor_sync(0xffffffffu, s,  o);
        sq += __shfl_xor_sync(0xffffffffu, sq, o);
    }
    const int warp = tid >> 5, lane = tid & 31;
    if (lane == 0) { rs[warp] = s; rq[warp] = sq; }
    __syncthreads();
    __shared__ float mu_s, rstd_s;
    if (tid == 0) {
        float S = 0.f, Q = 0.f;
        #pragma unroll
        for (int w = 0; w < 8; w++) { S += rs[w]; Q += rq[w]; }
        float mu = S * (1.0f / DM);
        float var = Q * (1.0f / DM) - mu * mu;
        mu_s = mu;
        rstd_s = rsqrtf(var + 1e-5f);
    }
    __syncthreads();
    float mu = mu_s, rstd = rstd_s;
    out[(size_t)row*DM + tid]       = (v0 - mu) * rstd * g[tid]       + be[tid];
    out[(size_t)row*DM + tid + 256] = (v1 - mu) * rstd * g[tid + 256] + be[tid + 256];
}

// ---------------- launch ----------------
extern "C" void kernel_launch(void* const* d_in, const int* in_sizes, int n_in,
                              void* d_out, int out_size)
{
    const float* q    = (const float*)d_in[0];
    const float* k    = (const float*)d_in[1];
    const float* v    = (const float*)d_in[2];
    const int*   mask = (const int*)d_in[3];
    const float* wq_w = (const float*)d_in[4];
    const float* wq_b = (const float*)d_in[5];
    const float* wk_w = (const float*)d_in[6];
    const float* wk_b = (const float*)d_in[7];
    const float* wv_w = (const float*)d_in[8];
    const float* wv_b = (const float*)d_in[9];
    const float* fc_w = (const float*)d_in[10];
    const float* fc_b = (const float*)d_in[11];
    const float* ln_g = (const float*)d_in[12];
    const float* ln_b = (const float*)d_in[13];

    float* out      = (float*)d_out;                       // [B, L, 512]
    float* attn_out = out + (size_t)MTOT * DM;             // [H*B, L, L]

    float *qh, *kh, *vh, *ao, *fc;
    cudaGetSymbolAddress((void**)&qh, g_qh);
    cudaGetSymbolAddress((void**)&kh, g_kh);
    cudaGetSymbolAddress((void**)&vh, g_vh);
    cudaGetSymbolAddress((void**)&ao, g_ao);
    cudaGetSymbolAddress((void**)&fc, g_fc);

    cudaFuncSetAttribute(attn_kernel, cudaFuncAttributeMaxDynamicSharedMemorySize, ATTN_SMEM);

    dim3 ggrid(DM/64, MTOT/64);
    gemm_kernel<<<ggrid, 256>>>(q, wq_w, wq_b, nullptr, qh, MTOT, DM, DM);
    gemm_kernel<<<ggrid, 256>>>(k, wk_w, wk_b, nullptr, kh, MTOT, DM, DM);
    gemm_kernel<<<ggrid, 256>>>(v, wv_w, wv_b, nullptr, vh, MTOT, DM, DM);

    dim3 agrid(LL/QT, NH, BB);
    attn_kernel<<<agrid, 256, ATTN_SMEM>>>(qh, kh, vh, mask, attn_out, ao);

    gemm_kernel<<<ggrid, 256>>>(ao, fc_w, fc_b, q, fc, MTOT, DM, DM);

    ln_kernel<<<MTOT, 256>>>(fc, ln_g, ln_b, out);
}